// round 11
// baseline (speedup 1.0000x reference)
#include <cuda_runtime.h>
#include <math.h>

#define B_  64
#define C_  512
#define HW_ 4096      // 64*64
#define E_  16
#define K_  4

// Scratch for pooled [B, C] (device global — no allocation)
__device__ float g_pooled[B_ * C_];

// ---------------------------------------------------------------------------
// Kernel 1: pooled[b,c] = max(x[b,c,:,:]) + mean(x[b,c,:,:])
// One warp per (b,c) row of 4096 contiguous floats. LOCKED — at the HBM roof.
// ---------------------------------------------------------------------------
__global__ __launch_bounds__(256) void pool_kernel(const float* __restrict__ x) {
    const int warp = (blockIdx.x * blockDim.x + threadIdx.x) >> 5;  // row in [0, B*C)
    const int lane = threadIdx.x & 31;

    const float4* __restrict__ p =
        reinterpret_cast<const float4*>(x + (size_t)warp * HW_);

    float mx0 = -INFINITY, mx1 = -INFINITY;
    float sm0 = 0.0f, sm1 = 0.0f;
#pragma unroll
    for (int i = 0; i < HW_ / 4 / 32; i += 2) {   // 32 float4 per lane, 2 chains
        float4 a = p[i * 32 + lane];
        float4 b = p[(i + 1) * 32 + lane];
        mx0 = fmaxf(mx0, fmaxf(fmaxf(a.x, a.y), fmaxf(a.z, a.w)));
        sm0 += (a.x + a.y) + (a.z + a.w);
        mx1 = fmaxf(mx1, fmaxf(fmaxf(b.x, b.y), fmaxf(b.z, b.w)));
        sm1 += (b.x + b.y) + (b.z + b.w);
    }
    float mx = fmaxf(mx0, mx1);
    float sm = sm0 + sm1;
#pragma unroll
    for (int o = 16; o; o >>= 1) {
        mx = fmaxf(mx, __shfl_xor_sync(0xffffffffu, mx, o));
        sm += __shfl_xor_sync(0xffffffffu, sm, o);
    }
    if (lane == 0) {
        g_pooled[warp] = mx + sm * (1.0f / HW_);
    }
}

// ---------------------------------------------------------------------------
// Kernel 2: lean gate. 64 blocks x 128 threads (4 warps). Warp w computes
// dots for experts 4w..4w+3; then warp 0 runs a fully warp-parallel epilogue
// (lane i owns expert i; width-16 butterflies; ballot-based top-K).
// ---------------------------------------------------------------------------
__global__ __launch_bounds__(128) void gate_kernel(const float* __restrict__ W0,
                                                   const float* __restrict__ b0,
                                                   const float* __restrict__ W1,
                                                   const float* __restrict__ b1,
                                                   float* __restrict__ out) {
    const int b    = blockIdx.x;
    const int tid  = threadIdx.x;
    const int w    = tid >> 5;     // warp 0..3
    const int lane = tid & 31;

    __shared__ float sh_h[E_];
    __shared__ float sh_n[E_];

    // pooled row fragment (shared by this warp's 4 experts)
    const float4* __restrict__ prow =
        reinterpret_cast<const float4*>(g_pooled + b * C_) + lane;
    float4 pv[4];
#pragma unroll
    for (int i = 0; i < 4; i++) pv[i] = prow[i * 32];

#pragma unroll
    for (int t = 0; t < 4; t++) {
        const int e = w * 4 + t;
        const float4* __restrict__ w0p =
            reinterpret_cast<const float4*>(W0 + e * C_) + lane;
        const float4* __restrict__ w1p =
            reinterpret_cast<const float4*>(W1 + e * C_) + lane;
        float d0 = 0.0f, d1 = 0.0f;
#pragma unroll
        for (int i = 0; i < 4; i++) {
            float4 w0 = w0p[i * 32];
            float4 w1 = w1p[i * 32];
            d0 = fmaf(pv[i].x, w0.x, d0); d0 = fmaf(pv[i].y, w0.y, d0);
            d0 = fmaf(pv[i].z, w0.z, d0); d0 = fmaf(pv[i].w, w0.w, d0);
            d1 = fmaf(pv[i].x, w1.x, d1); d1 = fmaf(pv[i].y, w1.y, d1);
            d1 = fmaf(pv[i].z, w1.z, d1); d1 = fmaf(pv[i].w, w1.w, d1);
        }
#pragma unroll
        for (int o = 16; o; o >>= 1) {
            d0 += __shfl_xor_sync(0xffffffffu, d0, o);
            d1 += __shfl_xor_sync(0xffffffffu, d1, o);
        }
        if (lane == 0) {
            float hv = d0 + b0[e];
            sh_h[e] = (hv >= 0.0f) ? hv : 0.2f * hv;                 // LeakyReLU
            float z = d1 + b1[e];
            sh_n[e] = fmaxf(z, 0.0f) + log1pf(expf(-fabsf(z)));      // softplus
        }
    }
    __syncthreads();

    // ------------- warp-parallel epilogue (warp 0; lane i = expert i) -------
    if (w == 0) {
        const bool act = lane < E_;
        float h  = act ? sh_h[lane] : 0.0f;
        float nz = act ? sh_n[lane] : 0.0f;

        // mean over 16 (width-16 butterfly keeps lanes 0-15 self-contained)
        float s = nz;
#pragma unroll
        for (int o = 8; o; o >>= 1) s += __shfl_xor_sync(0xffffffffu, s, o, 16);
        const float mu = s * (1.0f / E_);

        float d = nz - mu;
        float v = d * d;
#pragma unroll
        for (int o = 8; o; o >>= 1) v += __shfl_xor_sync(0xffffffffu, v, o, 16);
        const float sd = sqrtf(v * (1.0f / (E_ - 1)));   // ddof=1

        float score = act ? (h + d / sd) : -INFINITY;

        // top-K via max + ballot; lowest lane wins ties (= first occurrence)
        bool sel = false;
#pragma unroll
        for (int k = 0; k < K_; k++) {
            float cand = sel ? -INFINITY : score;
            float m = cand;
#pragma unroll
            for (int o = 8; o; o >>= 1)
                m = fmaxf(m, __shfl_xor_sync(0xffffffffu, m, o, 16));
            unsigned bal = __ballot_sync(0xffffffffu, !sel && score == m) & 0xffffu;
            int best = __ffs(bal) - 1;
            if (lane == best) sel = true;
        }

        // masked softmax over h
        float mh = sel ? h : -INFINITY;
#pragma unroll
        for (int o = 8; o; o >>= 1)
            mh = fmaxf(mh, __shfl_xor_sync(0xffffffffu, mh, o, 16));
        float g = sel ? expf(h - mh) : 0.0f;
        float gs = g;
#pragma unroll
        for (int o = 8; o; o >>= 1) gs += __shfl_xor_sync(0xffffffffu, gs, o, 16);

        if (act) out[b * E_ + lane] = g / gs;
    }
}

// ---------------------------------------------------------------------------
extern "C" void kernel_launch(void* const* d_in, const int* in_sizes, int n_in,
                              void* d_out, int out_size) {
    const float* x  = (const float*)d_in[0];
    const float* W0 = (const float*)d_in[1];
    const float* b0 = (const float*)d_in[2];
    const float* W1 = (const float*)d_in[3];
    const float* b1 = (const float*)d_in[4];
    float* out = (float*)d_out;

    pool_kernel<<<(B_ * C_) / 8, 256>>>(x);
    gate_kernel<<<B_, 128>>>(W0, b0, W1, b1, out);
}

// round 13
// speedup vs baseline: 1.0695x; 1.0695x over previous
#include <cuda_runtime.h>
#include <math.h>

#define B_  64
#define C_  512
#define HW_ 4096      // 64*64
#define E_  16
#define K_  4

// Scratch for pooled [B, C] (device global — no allocation)
__device__ float g_pooled[B_ * C_];

// ---------------------------------------------------------------------------
// Kernel 1: pooled[b,c] = max(x[b,c,:,:]) + mean(x[b,c,:,:])
// One warp per (b,c) row of 4096 contiguous floats. LOCKED — at the HBM roof.
// ---------------------------------------------------------------------------
__global__ __launch_bounds__(256) void pool_kernel(const float* __restrict__ x) {
    const int warp = (blockIdx.x * blockDim.x + threadIdx.x) >> 5;  // row in [0, B*C)
    const int lane = threadIdx.x & 31;

    const float4* __restrict__ p =
        reinterpret_cast<const float4*>(x + (size_t)warp * HW_);

    float mx0 = -INFINITY, mx1 = -INFINITY;
    float sm0 = 0.0f, sm1 = 0.0f;
#pragma unroll
    for (int i = 0; i < HW_ / 4 / 32; i += 2) {   // 32 float4 per lane, 2 chains
        float4 a = p[i * 32 + lane];
        float4 b = p[(i + 1) * 32 + lane];
        mx0 = fmaxf(mx0, fmaxf(fmaxf(a.x, a.y), fmaxf(a.z, a.w)));
        sm0 += (a.x + a.y) + (a.z + a.w);
        mx1 = fmaxf(mx1, fmaxf(fmaxf(b.x, b.y), fmaxf(b.z, b.w)));
        sm1 += (b.x + b.y) + (b.z + b.w);
    }
    float mx = fmaxf(mx0, mx1);
    float sm = sm0 + sm1;
#pragma unroll
    for (int o = 16; o; o >>= 1) {
        mx = fmaxf(mx, __shfl_xor_sync(0xffffffffu, mx, o));
        sm += __shfl_xor_sync(0xffffffffu, sm, o);
    }
    if (lane == 0) {
        g_pooled[warp] = mx + sm * (1.0f / HW_);
    }
}

// ---------------------------------------------------------------------------
// Kernel 2: gate. 64 blocks x 512 threads; warp e handles expert e with all
// weight loads front-batched (max MLP, one latency round). Warp 0 then runs
// the warp-parallel epilogue (lane i = expert i, width-16 butterflies,
// ballot-based top-K with first-occurrence tie-break).
// ---------------------------------------------------------------------------
__global__ __launch_bounds__(512) void gate_kernel(const float* __restrict__ W0,
                                                   const float* __restrict__ b0,
                                                   const float* __restrict__ W1,
                                                   const float* __restrict__ b1,
                                                   float* __restrict__ out) {
    const int b    = blockIdx.x;
    const int tid  = threadIdx.x;
    const int e    = tid >> 5;     // expert = warp id (0..15)
    const int lane = tid & 31;

    __shared__ float sh_h[E_];
    __shared__ float sh_n[E_];

    // Front-batch ALL loads: 4+4 weight LDG.128 + 4 pooled LDG.128 per lane
    const float4* __restrict__ w0p =
        reinterpret_cast<const float4*>(W0 + e * C_) + lane;
    const float4* __restrict__ w1p =
        reinterpret_cast<const float4*>(W1 + e * C_) + lane;
    const float4* __restrict__ prow =
        reinterpret_cast<const float4*>(g_pooled + b * C_) + lane;

    float4 w0r[4], w1r[4], pv[4];
#pragma unroll
    for (int i = 0; i < 4; i++) pv[i]  = prow[i * 32];
#pragma unroll
    for (int i = 0; i < 4; i++) w0r[i] = w0p[i * 32];
#pragma unroll
    for (int i = 0; i < 4; i++) w1r[i] = w1p[i * 32];

    float d0 = 0.0f, d1 = 0.0f;
#pragma unroll
    for (int i = 0; i < 4; i++) {
        d0 = fmaf(pv[i].x, w0r[i].x, d0); d0 = fmaf(pv[i].y, w0r[i].y, d0);
        d0 = fmaf(pv[i].z, w0r[i].z, d0); d0 = fmaf(pv[i].w, w0r[i].w, d0);
        d1 = fmaf(pv[i].x, w1r[i].x, d1); d1 = fmaf(pv[i].y, w1r[i].y, d1);
        d1 = fmaf(pv[i].z, w1r[i].z, d1); d1 = fmaf(pv[i].w, w1r[i].w, d1);
    }
#pragma unroll
    for (int o = 16; o; o >>= 1) {
        d0 += __shfl_xor_sync(0xffffffffu, d0, o);
        d1 += __shfl_xor_sync(0xffffffffu, d1, o);
    }
    if (lane == 0) {
        float hv = d0 + b0[e];
        sh_h[e] = (hv >= 0.0f) ? hv : 0.2f * hv;                 // LeakyReLU(0.2)
        float z = d1 + b1[e];
        sh_n[e] = fmaxf(z, 0.0f) + log1pf(expf(-fabsf(z)));      // softplus
    }
    __syncthreads();

    // ------------- warp-parallel epilogue (warp 0; lane i = expert i) -------
    if (tid < 32) {
        const bool act = lane < E_;
        float h  = act ? sh_h[lane] : 0.0f;
        float nz = act ? sh_n[lane] : 0.0f;

        // mean over 16 (width-16 butterfly keeps lanes 0-15 self-contained)
        float s = nz;
#pragma unroll
        for (int o = 8; o; o >>= 1) s += __shfl_xor_sync(0xffffffffu, s, o, 16);
        const float mu = s * (1.0f / E_);

        float d = nz - mu;
        float v = d * d;
#pragma unroll
        for (int o = 8; o; o >>= 1) v += __shfl_xor_sync(0xffffffffu, v, o, 16);
        const float sd = sqrtf(v * (1.0f / (E_ - 1)));   // ddof=1

        float score = act ? (h + d / sd) : -INFINITY;

        // top-K via max + ballot; lowest lane wins ties (= first occurrence)
        bool sel = false;
#pragma unroll
        for (int k = 0; k < K_; k++) {
            float cand = sel ? -INFINITY : score;
            float m = cand;
#pragma unroll
            for (int o = 8; o; o >>= 1)
                m = fmaxf(m, __shfl_xor_sync(0xffffffffu, m, o, 16));
            unsigned bal = __ballot_sync(0xffffffffu, !sel && score == m) & 0xffffu;
            int best = __ffs(bal) - 1;
            if (lane == best) sel = true;
        }

        // masked softmax over h
        float mh = sel ? h : -INFINITY;
#pragma unroll
        for (int o = 8; o; o >>= 1)
            mh = fmaxf(mh, __shfl_xor_sync(0xffffffffu, mh, o, 16));
        float g = sel ? expf(h - mh) : 0.0f;
        float gs = g;
#pragma unroll
        for (int o = 8; o; o >>= 1) gs += __shfl_xor_sync(0xffffffffu, gs, o, 16);

        if (act) out[b * E_ + lane] = g / gs;
    }
}

// ---------------------------------------------------------------------------
extern "C" void kernel_launch(void* const* d_in, const int* in_sizes, int n_in,
                              void* d_out, int out_size) {
    const float* x  = (const float*)d_in[0];
    const float* W0 = (const float*)d_in[1];
    const float* b0 = (const float*)d_in[2];
    const float* W1 = (const float*)d_in[3];
    const float* b1 = (const float*)d_in[4];
    float* out = (float*)d_out;

    pool_kernel<<<(B_ * C_) / 8, 256>>>(x);
    gate_kernel<<<B_, 512>>>(W0, b0, W1, b1, out);
}

// round 14
// speedup vs baseline: 1.0745x; 1.0047x over previous
#include <cuda_runtime.h>
#include <math.h>

#define B_  64
#define C_  512
#define HW_ 4096      // 64*64
#define E_  16
#define K_  4

// Scratch for pooled [B, C] (device global — no allocation)
__device__ float g_pooled[B_ * C_];

// ---------------------------------------------------------------------------
// Kernel 1: pooled[b,c] = max(x) + mean(x) over each row of 4096 floats.
// Row split across 4 warps (1024 contiguous floats each) to cut per-row
// completion time 4x and shrink the end-of-grid drain tail.
// Block = 256 threads = 8 warps = 2 rows.
// ---------------------------------------------------------------------------
__global__ __launch_bounds__(256) void pool_kernel(const float* __restrict__ x) {
    const int tid  = threadIdx.x;
    const int w    = tid >> 5;          // warp 0..7
    const int lane = tid & 31;
    const int rloc = w >> 2;            // row within block (0..1)
    const int q    = w & 3;             // quarter of the row (0..3)
    const int row  = blockIdx.x * 2 + rloc;

    __shared__ float2 sh[8];            // per-warp (max, sum) partials

    // quarter = 1024 floats = 256 float4; 8 float4 per lane, front-batched
    const float4* __restrict__ p =
        reinterpret_cast<const float4*>(x + (size_t)row * HW_) + q * 256 + lane;

    float mx0 = -INFINITY, mx1 = -INFINITY;
    float sm0 = 0.0f, sm1 = 0.0f;
#pragma unroll
    for (int i = 0; i < 8; i += 2) {
        float4 a = p[i * 32];
        float4 b = p[(i + 1) * 32];
        mx0 = fmaxf(mx0, fmaxf(fmaxf(a.x, a.y), fmaxf(a.z, a.w)));
        sm0 += (a.x + a.y) + (a.z + a.w);
        mx1 = fmaxf(mx1, fmaxf(fmaxf(b.x, b.y), fmaxf(b.z, b.w)));
        sm1 += (b.x + b.y) + (b.z + b.w);
    }
    float mx = fmaxf(mx0, mx1);
    float sm = sm0 + sm1;
#pragma unroll
    for (int o = 16; o; o >>= 1) {
        mx = fmaxf(mx, __shfl_xor_sync(0xffffffffu, mx, o));
        sm += __shfl_xor_sync(0xffffffffu, sm, o);
    }
    if (lane == 0) sh[w] = make_float2(mx, sm);
    __syncthreads();

    if (tid < 2) {                      // thread r combines row r's 4 quarters
        float2 a = sh[tid * 4 + 0], b = sh[tid * 4 + 1];
        float2 c = sh[tid * 4 + 2], d = sh[tid * 4 + 3];
        float m = fmaxf(fmaxf(a.x, b.x), fmaxf(c.x, d.x));
        float s = (a.y + b.y) + (c.y + d.y);
        g_pooled[blockIdx.x * 2 + tid] = m + s * (1.0f / HW_);
    }
}

// ---------------------------------------------------------------------------
// Kernel 2: gate (R13 champion form). 64 blocks x 512 threads; warp e =
// expert e, all loads front-batched; warp 0 runs the warp-parallel epilogue.
// ---------------------------------------------------------------------------
__global__ __launch_bounds__(512) void gate_kernel(const float* __restrict__ W0,
                                                   const float* __restrict__ b0,
                                                   const float* __restrict__ W1,
                                                   const float* __restrict__ b1,
                                                   float* __restrict__ out) {
    const int b    = blockIdx.x;
    const int tid  = threadIdx.x;
    const int e    = tid >> 5;     // expert = warp id (0..15)
    const int lane = tid & 31;

    __shared__ float sh_h[E_];
    __shared__ float sh_n[E_];

    const float4* __restrict__ w0p =
        reinterpret_cast<const float4*>(W0 + e * C_) + lane;
    const float4* __restrict__ w1p =
        reinterpret_cast<const float4*>(W1 + e * C_) + lane;
    const float4* __restrict__ prow =
        reinterpret_cast<const float4*>(g_pooled + b * C_) + lane;

    float4 w0r[4], w1r[4], pv[4];
#pragma unroll
    for (int i = 0; i < 4; i++) pv[i]  = prow[i * 32];
#pragma unroll
    for (int i = 0; i < 4; i++) w0r[i] = w0p[i * 32];
#pragma unroll
    for (int i = 0; i < 4; i++) w1r[i] = w1p[i * 32];

    float d0 = 0.0f, d1 = 0.0f;
#pragma unroll
    for (int i = 0; i < 4; i++) {
        d0 = fmaf(pv[i].x, w0r[i].x, d0); d0 = fmaf(pv[i].y, w0r[i].y, d0);
        d0 = fmaf(pv[i].z, w0r[i].z, d0); d0 = fmaf(pv[i].w, w0r[i].w, d0);
        d1 = fmaf(pv[i].x, w1r[i].x, d1); d1 = fmaf(pv[i].y, w1r[i].y, d1);
        d1 = fmaf(pv[i].z, w1r[i].z, d1); d1 = fmaf(pv[i].w, w1r[i].w, d1);
    }
#pragma unroll
    for (int o = 16; o; o >>= 1) {
        d0 += __shfl_xor_sync(0xffffffffu, d0, o);
        d1 += __shfl_xor_sync(0xffffffffu, d1, o);
    }
    if (lane == 0) {
        float hv = d0 + b0[e];
        sh_h[e] = (hv >= 0.0f) ? hv : 0.2f * hv;                 // LeakyReLU(0.2)
        float z = d1 + b1[e];
        sh_n[e] = fmaxf(z, 0.0f) + log1pf(expf(-fabsf(z)));      // softplus
    }
    __syncthreads();

    // ------------- warp-parallel epilogue (warp 0; lane i = expert i) -------
    if (tid < 32) {
        const bool act = lane < E_;
        float h  = act ? sh_h[lane] : 0.0f;
        float nz = act ? sh_n[lane] : 0.0f;

        float s = nz;
#pragma unroll
        for (int o = 8; o; o >>= 1) s += __shfl_xor_sync(0xffffffffu, s, o, 16);
        const float mu = s * (1.0f / E_);

        float d = nz - mu;
        float v = d * d;
#pragma unroll
        for (int o = 8; o; o >>= 1) v += __shfl_xor_sync(0xffffffffu, v, o, 16);
        const float sd = sqrtf(v * (1.0f / (E_ - 1)));   // ddof=1

        float score = act ? (h + d / sd) : -INFINITY;

        // top-K via max + ballot; lowest lane wins ties (= first occurrence)
        bool sel = false;
#pragma unroll
        for (int k = 0; k < K_; k++) {
            float cand = sel ? -INFINITY : score;
            float m = cand;
#pragma unroll
            for (int o = 8; o; o >>= 1)
                m = fmaxf(m, __shfl_xor_sync(0xffffffffu, m, o, 16));
            unsigned bal = __ballot_sync(0xffffffffu, !sel && score == m) & 0xffffu;
            int best = __ffs(bal) - 1;
            if (lane == best) sel = true;
        }

        float mh = sel ? h : -INFINITY;
#pragma unroll
        for (int o = 8; o; o >>= 1)
            mh = fmaxf(mh, __shfl_xor_sync(0xffffffffu, mh, o, 16));
        float g = sel ? expf(h - mh) : 0.0f;
        float gs = g;
#pragma unroll
        for (int o = 8; o; o >>= 1) gs += __shfl_xor_sync(0xffffffffu, gs, o, 16);

        if (act) out[b * E_ + lane] = g / gs;
    }
}

// ---------------------------------------------------------------------------
extern "C" void kernel_launch(void* const* d_in, const int* in_sizes, int n_in,
                              void* d_out, int out_size) {
    const float* x  = (const float*)d_in[0];
    const float* W0 = (const float*)d_in[1];
    const float* b0 = (const float*)d_in[2];
    const float* W1 = (const float*)d_in[3];
    const float* b1 = (const float*)d_in[4];
    float* out = (float*)d_out;

    pool_kernel<<<(B_ * C_) / 2, 256>>>(x);   // 2 rows per block
    gate_kernel<<<B_, 512>>>(W0, b0, W1, b1, out);
}

// round 15
// speedup vs baseline: 1.0967x; 1.0207x over previous
#include <cuda_runtime.h>
#include <math.h>

#define B_  64
#define C_  512
#define HW_ 4096      // 64*64
#define E_  16
#define K_  4

// Scratch for pooled [B, C] (device global — no allocation)
__device__ float g_pooled[B_ * C_];

// ---------------------------------------------------------------------------
// Kernel 1: pooled[b,c] = max(x) + mean(x) over each row of 4096 floats.
// Row split across 4 warps (1024 contiguous floats each); block = 2 rows.
// x is read-once -> streaming loads (__ldcs, evict-first) to avoid L2 churn.
// ---------------------------------------------------------------------------
__global__ __launch_bounds__(256) void pool_kernel(const float* __restrict__ x) {
    const int tid  = threadIdx.x;
    const int w    = tid >> 5;          // warp 0..7
    const int lane = tid & 31;
    const int rloc = w >> 2;            // row within block (0..1)
    const int q    = w & 3;             // quarter of the row (0..3)
    const int row  = blockIdx.x * 2 + rloc;

    __shared__ float2 sh[8];            // per-warp (max, sum) partials

    // quarter = 1024 floats = 256 float4; 8 float4 per lane, front-batched
    const float4* __restrict__ p =
        reinterpret_cast<const float4*>(x + (size_t)row * HW_) + q * 256 + lane;

    float mx0 = -INFINITY, mx1 = -INFINITY;
    float sm0 = 0.0f, sm1 = 0.0f;
#pragma unroll
    for (int i = 0; i < 8; i += 2) {
        float4 a = __ldcs(p + i * 32);          // streaming: evict-first
        float4 b = __ldcs(p + (i + 1) * 32);
        mx0 = fmaxf(mx0, fmaxf(fmaxf(a.x, a.y), fmaxf(a.z, a.w)));
        sm0 += (a.x + a.y) + (a.z + a.w);
        mx1 = fmaxf(mx1, fmaxf(fmaxf(b.x, b.y), fmaxf(b.z, b.w)));
        sm1 += (b.x + b.y) + (b.z + b.w);
    }
    float mx = fmaxf(mx0, mx1);
    float sm = sm0 + sm1;
#pragma unroll
    for (int o = 16; o; o >>= 1) {
        mx = fmaxf(mx, __shfl_xor_sync(0xffffffffu, mx, o));
        sm += __shfl_xor_sync(0xffffffffu, sm, o);
    }
    if (lane == 0) sh[w] = make_float2(mx, sm);
    __syncthreads();

    if (tid < 2) {                      // thread r combines row r's 4 quarters
        float2 a = sh[tid * 4 + 0], b = sh[tid * 4 + 1];
        float2 c = sh[tid * 4 + 2], d = sh[tid * 4 + 3];
        float m = fmaxf(fmaxf(a.x, b.x), fmaxf(c.x, d.x));
        float s = (a.y + b.y) + (c.y + d.y);
        g_pooled[blockIdx.x * 2 + tid] = m + s * (1.0f / HW_);
    }
}

// ---------------------------------------------------------------------------
// Kernel 2: gate (champion form). 64 blocks x 512 threads; warp e = expert e,
// all loads front-batched; warp 0 runs the warp-parallel epilogue.
// ---------------------------------------------------------------------------
__global__ __launch_bounds__(512) void gate_kernel(const float* __restrict__ W0,
                                                   const float* __restrict__ b0,
                                                   const float* __restrict__ W1,
                                                   const float* __restrict__ b1,
                                                   float* __restrict__ out) {
    const int b    = blockIdx.x;
    const int tid  = threadIdx.x;
    const int e    = tid >> 5;     // expert = warp id (0..15)
    const int lane = tid & 31;

    __shared__ float sh_h[E_];
    __shared__ float sh_n[E_];

    const float4* __restrict__ w0p =
        reinterpret_cast<const float4*>(W0 + e * C_) + lane;
    const float4* __restrict__ w1p =
        reinterpret_cast<const float4*>(W1 + e * C_) + lane;
    const float4* __restrict__ prow =
        reinterpret_cast<const float4*>(g_pooled + b * C_) + lane;

    float4 w0r[4], w1r[4], pv[4];
#pragma unroll
    for (int i = 0; i < 4; i++) pv[i]  = prow[i * 32];
#pragma unroll
    for (int i = 0; i < 4; i++) w0r[i] = w0p[i * 32];
#pragma unroll
    for (int i = 0; i < 4; i++) w1r[i] = w1p[i * 32];

    float d0 = 0.0f, d1 = 0.0f;
#pragma unroll
    for (int i = 0; i < 4; i++) {
        d0 = fmaf(pv[i].x, w0r[i].x, d0); d0 = fmaf(pv[i].y, w0r[i].y, d0);
        d0 = fmaf(pv[i].z, w0r[i].z, d0); d0 = fmaf(pv[i].w, w0r[i].w, d0);
        d1 = fmaf(pv[i].x, w1r[i].x, d1); d1 = fmaf(pv[i].y, w1r[i].y, d1);
        d1 = fmaf(pv[i].z, w1r[i].z, d1); d1 = fmaf(pv[i].w, w1r[i].w, d1);
    }
#pragma unroll
    for (int o = 16; o; o >>= 1) {
        d0 += __shfl_xor_sync(0xffffffffu, d0, o);
        d1 += __shfl_xor_sync(0xffffffffu, d1, o);
    }
    if (lane == 0) {
        float hv = d0 + b0[e];
        sh_h[e] = (hv >= 0.0f) ? hv : 0.2f * hv;                 // LeakyReLU(0.2)
        float z = d1 + b1[e];
        sh_n[e] = fmaxf(z, 0.0f) + log1pf(expf(-fabsf(z)));      // softplus
    }
    __syncthreads();

    // ------------- warp-parallel epilogue (warp 0; lane i = expert i) -------
    if (tid < 32) {
        const bool act = lane < E_;
        float h  = act ? sh_h[lane] : 0.0f;
        float nz = act ? sh_n[lane] : 0.0f;

        float s = nz;
#pragma unroll
        for (int o = 8; o; o >>= 1) s += __shfl_xor_sync(0xffffffffu, s, o, 16);
        const float mu = s * (1.0f / E_);

        float d = nz - mu;
        float v = d * d;
#pragma unroll
        for (int o = 8; o; o >>= 1) v += __shfl_xor_sync(0xffffffffu, v, o, 16);
        const float sd = sqrtf(v * (1.0f / (E_ - 1)));   // ddof=1

        float score = act ? (h + d / sd) : -INFINITY;

        // top-K via max + ballot; lowest lane wins ties (= first occurrence)
        bool sel = false;
#pragma unroll
        for (int k = 0; k < K_; k++) {
            float cand = sel ? -INFINITY : score;
            float m = cand;
#pragma unroll
            for (int o = 8; o; o >>= 1)
                m = fmaxf(m, __shfl_xor_sync(0xffffffffu, m, o, 16));
            unsigned bal = __ballot_sync(0xffffffffu, !sel && score == m) & 0xffffu;
            int best = __ffs(bal) - 1;
            if (lane == best) sel = true;
        }

        float mh = sel ? h : -INFINITY;
#pragma unroll
        for (int o = 8; o; o >>= 1)
            mh = fmaxf(mh, __shfl_xor_sync(0xffffffffu, mh, o, 16));
        float g = sel ? expf(h - mh) : 0.0f;
        float gs = g;
#pragma unroll
        for (int o = 8; o; o >>= 1) gs += __shfl_xor_sync(0xffffffffu, gs, o, 16);

        if (act) out[b * E_ + lane] = g / gs;
    }
}

// ---------------------------------------------------------------------------
extern "C" void kernel_launch(void* const* d_in, const int* in_sizes, int n_in,
                              void* d_out, int out_size) {
    const float* x  = (const float*)d_in[0];
    const float* W0 = (const float*)d_in[1];
    const float* b0 = (const float*)d_in[2];
    const float* W1 = (const float*)d_in[3];
    const float* b1 = (const float*)d_in[4];
    float* out = (float*)d_out;

    pool_kernel<<<(B_ * C_) / 2, 256>>>(x);   // 2 rows per block
    gate_kernel<<<B_, 512>>>(W0, b0, W1, b1, out);
}